// round 3
// baseline (speedup 1.0000x reference)
#include <cuda_runtime.h>
#include <math.h>

#define NB 16
#define NT 128
#define NI 8
#define ND 128
#define NRB (NT*NB)   // 2048

// scratch (allowed: __device__ globals)
__device__ float g_Xd[NRB*ND];
__device__ float g_T [NRB*ND];
__device__ float g_Z [NRB*ND];

// mask is a bool array delivered as 32-bit elements (int32 0/1 or float32 0.0/1.0).
// Reading the 32-bit word and testing !=0 is correct for both encodings.
__device__ __forceinline__ float mask_f(const unsigned int* __restrict__ m, int idx){
    return (m[idx] != 0u) ? 1.0f : 0.0f;
}

__device__ __forceinline__ float gelu_f(float x){
    // jax gelu (tanh approx) == x * sigmoid(2*g), g = sqrt(2/pi)*(x + 0.044715 x^3)
    float x2 = x*x;
    float g  = x*(0.7978845608028654f + 0.03567740813634427f*x2);
    float e  = __expf(-2.0f*g);
    return x / (1.0f + e);
}

// ---------------------------------------------------------------------------
// x_diag[rb][d]: embed + gelu + mask + LN1 of the diagonal rows
// ---------------------------------------------------------------------------
__global__ void __launch_bounds__(128) k_diag(
    const float* __restrict__ vec, const unsigned int* __restrict__ mask,
    const float* __restrict__ We,  const float* __restrict__ be,
    const float* __restrict__ g1,  const float* __restrict__ b1)
{
    int rb = blockIdx.x; int r = rb >> 4; int b = rb & 15;
    int d  = threadIdx.x;
    __shared__ float v8[8];
    __shared__ float red[8];
    const float* vp = vec + ((b*NT + r)*NT + r)*NI;
    if (d < 8) v8[d] = vp[d];
    float mf = mask_f(mask, (b*NT + r)*NT + r);
    __syncthreads();
    float y = be[d];
    #pragma unroll
    for (int i = 0; i < 8; i++) y += v8[i]*We[i*ND + d];
    y = gelu_f(y) * mf;
    float s1 = y, s2 = y*y;
    #pragma unroll
    for (int o = 16; o; o >>= 1){
        s1 += __shfl_xor_sync(0xffffffffu, s1, o);
        s2 += __shfl_xor_sync(0xffffffffu, s2, o);
    }
    int w = d >> 5, lane = d & 31;
    if (lane == 0){ red[w] = s1; red[4+w] = s2; }
    __syncthreads();
    s1 = red[0]+red[1]+red[2]+red[3];
    s2 = red[4]+red[5]+red[6]+red[7];
    float mu  = s1 * (1.0f/128.0f);
    float var = s2 * (1.0f/128.0f) - mu*mu;
    float o   = (y - mu)*rsqrtf(var + 1e-5f)*g1[d] + b1[d];
    g_Xd[rb*ND + d] = o;
}

// ---------------------------------------------------------------------------
// T = (Xd @ Wq) @ Wk^T     (fused 2-GEMM, 32-row tiles, 64 CTAs x 256 thr)
// ---------------------------------------------------------------------------
__global__ void __launch_bounds__(256) k_qt(
    const float* __restrict__ Wq, const float* __restrict__ Wk)
{
    __shared__ float sA[32*132];
    int tid = threadIdx.x;
    int rb0 = blockIdx.x*32;
    for (int idx = tid; idx < 32*128; idx += 256){
        int row = idx >> 7, col = idx & 127;
        sA[row*132 + col] = g_Xd[(rb0+row)*ND + col];
    }
    __syncthreads();
    int ty = tid >> 4, tx = tid & 15;     // ty: 16 groups of 2 rows, tx: 16 groups of 8 cols
    float acc[2][8];
    #pragma unroll
    for (int i=0;i<2;i++)
        #pragma unroll
        for (int j=0;j<8;j++) acc[i][j] = 0.0f;
    for (int k = 0; k < 128; k++){
        float a0 = sA[(2*ty+0)*132 + k];
        float a1 = sA[(2*ty+1)*132 + k];
        float4 bA = *(const float4*)(Wq + k*ND + 8*tx);
        float4 bB = *(const float4*)(Wq + k*ND + 8*tx + 4);
        float bb[8] = {bA.x,bA.y,bA.z,bA.w,bB.x,bB.y,bB.z,bB.w};
        #pragma unroll
        for (int j=0;j<8;j++){ acc[0][j] += a0*bb[j]; acc[1][j] += a1*bb[j]; }
    }
    __syncthreads();
    #pragma unroll
    for (int i=0;i<2;i++)
        #pragma unroll
        for (int j=0;j<8;j++) sA[(2*ty+i)*132 + 8*tx + j] = acc[i][j];
    __syncthreads();
    float ac2[2][8];
    #pragma unroll
    for (int i=0;i<2;i++)
        #pragma unroll
        for (int j=0;j<8;j++) ac2[i][j] = 0.0f;
    for (int k = 0; k < 128; k++){
        float a0 = sA[(2*ty+0)*132 + k];
        float a1 = sA[(2*ty+1)*132 + k];
        #pragma unroll
        for (int j=0;j<8;j++){
            float bv = Wk[(8*tx+j)*ND + k];   // Wk^T access
            ac2[0][j] += a0*bv; ac2[1][j] += a1*bv;
        }
    }
    #pragma unroll
    for (int i=0;i<2;i++)
        #pragma unroll
        for (int j=0;j<8;j++) g_T[(rb0+2*ty+i)*ND + 8*tx + j] = ac2[i][j];
}

// ---------------------------------------------------------------------------
// Fused attention: per (r,b) recompute x rows in 32-row chunks, online softmax,
// z[rb][d] = sum_c softmax(x_row . t)[c] * x_row[c][d]
// ---------------------------------------------------------------------------
__global__ void __launch_bounds__(128) k_attn(
    const float* __restrict__ vec, const unsigned int* __restrict__ mask,
    const float* __restrict__ We,  const float* __restrict__ be,
    const float* __restrict__ g1,  const float* __restrict__ b1)
{
    __shared__ float sWe[8*128];
    __shared__ float sbe[128], sg1[128], sb1[128];
    __shared__ float ts[128];
    __shared__ float sxs[32*132];
    __shared__ float sv8[32*8];
    __shared__ float smk[32];
    __shared__ float slg[32];
    __shared__ float sw[32];
    __shared__ float sml[2];

    int tid = threadIdx.x;
    int rb = blockIdx.x; int r = rb >> 4; int b = rb & 15;

    for (int idx = tid; idx < 1024; idx += 128) sWe[idx] = We[idx];
    sbe[tid] = be[tid]; sg1[tid] = g1[tid]; sb1[tid] = b1[tid];
    ts[tid]  = g_T[rb*ND + tid] * 0.08838834764831845f;   // 1/sqrt(128)
    __syncthreads();

    int cl = tid >> 2, q = tid & 3;
    const float* vbase = vec + ((b*NT + r)*NT)*NI;
    const unsigned int* mbase = mask + (b*NT + r)*NT;

    float m_run = -INFINITY, l_run = 0.0f;   // meaningful in warp0 only
    float zacc = 0.0f;

    for (int c0 = 0; c0 < NT; c0 += 32){
        for (int idx = tid; idx < 256; idx += 128) sv8[idx] = vbase[c0*NI + idx];
        if (tid < 32) smk[tid] = mask_f(mbase, c0 + tid);
        __syncthreads();

        float v8r[8];
        #pragma unroll
        for (int i = 0; i < 8; i++) v8r[i] = sv8[cl*8 + i];
        float mf = smk[cl];
        float y[32];
        float s1 = 0.0f, s2 = 0.0f;
        #pragma unroll
        for (int j = 0; j < 32; j++){
            int d = q + 4*j;
            float acc = sbe[d];
            #pragma unroll
            for (int i = 0; i < 8; i++) acc += v8r[i]*sWe[i*128 + d];
            acc = gelu_f(acc)*mf;
            y[j] = acc; s1 += acc; s2 += acc*acc;
        }
        s1 += __shfl_xor_sync(0xffffffffu, s1, 1); s2 += __shfl_xor_sync(0xffffffffu, s2, 1);
        s1 += __shfl_xor_sync(0xffffffffu, s1, 2); s2 += __shfl_xor_sync(0xffffffffu, s2, 2);
        float mu   = s1*(1.0f/128.0f);
        float var  = s2*(1.0f/128.0f) - mu*mu;
        float rstd = rsqrtf(var + 1e-5f);
        float dotp = 0.0f;
        #pragma unroll
        for (int j = 0; j < 32; j++){
            int d = q + 4*j;
            float xv = (y[j] - mu)*rstd*sg1[d] + sb1[d];
            sxs[cl*132 + d] = xv;
            dotp += xv * ts[d];
        }
        dotp += __shfl_xor_sync(0xffffffffu, dotp, 1);
        dotp += __shfl_xor_sync(0xffffffffu, dotp, 2);
        bool am = (mf != 0.0f) || (c0 + cl == r);
        float lg = dotp + (am ? 0.0f : -1e9f);
        if (q == 0) slg[cl] = lg;
        __syncthreads();

        if (tid < 32){
            float lgv = slg[tid];
            float cm = lgv;
            #pragma unroll
            for (int o = 16; o; o >>= 1) cm = fmaxf(cm, __shfl_xor_sync(0xffffffffu, cm, o));
            float m_new = fmaxf(m_run, cm);
            float corr  = __expf(m_run - m_new);
            float w     = __expf(lgv - m_new);
            float s = w;
            #pragma unroll
            for (int o = 16; o; o >>= 1) s += __shfl_xor_sync(0xffffffffu, s, o);
            sw[tid] = w;
            l_run = l_run*corr + s;
            m_run = m_new;
            if (tid == 0) sml[0] = corr;
        }
        __syncthreads();
        float corr = sml[0];
        zacc *= corr;
        #pragma unroll
        for (int c = 0; c < 32; c++) zacc += sw[c]*sxs[c*132 + tid];
        __syncthreads();
    }
    if (tid == 0) sml[1] = l_run;
    __syncthreads();
    g_Z[rb*ND + tid] = zacc / sml[1];
}

// ---------------------------------------------------------------------------
// E = Z@Wv ; H = gelu(E@Wout + bo) ; out = LN2(H+E)*seq   (32-row tiles)
// ---------------------------------------------------------------------------
__global__ void __launch_bounds__(256) k_out(
    const float* __restrict__ Wv, const float* __restrict__ Wo,
    const float* __restrict__ bo, const float* __restrict__ g2,
    const float* __restrict__ b2, const unsigned int* __restrict__ mask,
    float* __restrict__ out)
{
    __shared__ float sA[32*132];
    int tid = threadIdx.x;
    int rb0 = blockIdx.x*32;
    for (int idx = tid; idx < 32*128; idx += 256){
        int row = idx >> 7, col = idx & 127;
        sA[row*132 + col] = g_Z[(rb0+row)*ND + col];
    }
    __syncthreads();
    int ty = tid >> 4, tx = tid & 15;
    float acc[2][8];
    #pragma unroll
    for (int i=0;i<2;i++)
        #pragma unroll
        for (int j=0;j<8;j++) acc[i][j] = 0.0f;
    for (int k = 0; k < 128; k++){
        float a0 = sA[(2*ty+0)*132 + k];
        float a1 = sA[(2*ty+1)*132 + k];
        float4 bA = *(const float4*)(Wv + k*ND + 8*tx);
        float4 bB = *(const float4*)(Wv + k*ND + 8*tx + 4);
        float bb[8] = {bA.x,bA.y,bA.z,bA.w,bB.x,bB.y,bB.z,bB.w};
        #pragma unroll
        for (int j=0;j<8;j++){ acc[0][j] += a0*bb[j]; acc[1][j] += a1*bb[j]; }
    }
    __syncthreads();
    #pragma unroll
    for (int i=0;i<2;i++)
        #pragma unroll
        for (int j=0;j<8;j++) sA[(2*ty+i)*132 + 8*tx + j] = acc[i][j];   // E
    __syncthreads();
    float ac2[2][8];
    #pragma unroll
    for (int i=0;i<2;i++)
        #pragma unroll
        for (int j=0;j<8;j++) ac2[i][j] = bo[8*tx + j];
    for (int k = 0; k < 128; k++){
        float a0 = sA[(2*ty+0)*132 + k];
        float a1 = sA[(2*ty+1)*132 + k];
        float4 bA = *(const float4*)(Wo + k*ND + 8*tx);
        float4 bB = *(const float4*)(Wo + k*ND + 8*tx + 4);
        float bb[8] = {bA.x,bA.y,bA.z,bA.w,bB.x,bB.y,bB.z,bB.w};
        #pragma unroll
        for (int j=0;j<8;j++){ ac2[0][j] += a0*bb[j]; ac2[1][j] += a1*bb[j]; }
    }
    __syncthreads();
    #pragma unroll
    for (int i=0;i<2;i++)
        #pragma unroll
        for (int j=0;j<8;j++){
            int a = (2*ty+i)*132 + 8*tx + j;
            float e = sA[a];
            sA[a] = gelu_f(ac2[i][j]) + e;   // t = gelu(H)+E, in place (post-sync)
        }
    __syncthreads();
    if (tid < 128){
        int row = tid >> 2, q = tid & 3;
        float s1 = 0.0f, s2 = 0.0f;
        #pragma unroll
        for (int j = 0; j < 32; j++){
            float v = sA[row*132 + q + 4*j];
            s1 += v; s2 += v*v;
        }
        s1 += __shfl_xor_sync(0xffffffffu, s1, 1); s2 += __shfl_xor_sync(0xffffffffu, s2, 1);
        s1 += __shfl_xor_sync(0xffffffffu, s1, 2); s2 += __shfl_xor_sync(0xffffffffu, s2, 2);
        float mu   = s1*(1.0f/128.0f);
        float var  = s2*(1.0f/128.0f) - mu*mu;
        float rstd = rsqrtf(var + 1e-5f);
        int rbg = rb0 + row; int r = rbg >> 4, bb = rbg & 15;
        float sf = mask_f(mask, (bb*NT + r)*NT + r);
        #pragma unroll
        for (int j = 0; j < 32; j++){
            int d = q + 4*j;
            float v = sA[row*132 + d];
            out[rbg*ND + d] = ((v - mu)*rstd*g2[d] + b2[d])*sf;
        }
    }
}

// ---------------------------------------------------------------------------
// bool outputs as float: padding_mask (B,T), sequence_mask (T,B,1), global (T)
// ---------------------------------------------------------------------------
__global__ void k_masks(const unsigned int* __restrict__ mask, float* __restrict__ out)
{
    int idx = blockIdx.x*blockDim.x + threadIdx.x;
    if (idx < 2048){
        int b = idx >> 7, t = idx & 127;
        out[262144 + idx] = (mask[(b*NT + t)*NT + t] != 0u) ? 0.0f : 1.0f;   // ~seq^T
    } else if (idx < 4096){
        int k = idx - 2048; int t = k >> 4, b = k & 15;
        out[264192 + k] = (mask[(b*NT + t)*NT + t] != 0u) ? 1.0f : 0.0f;     // seq
    } else if (idx < 4224){
        out[266240 + (idx - 4096)] = 1.0f;                                    // ones
    }
}

extern "C" void kernel_launch(void* const* d_in, const int* in_sizes, int n_in,
                              void* d_out, int out_size)
{
    const float*        vec  = (const float*)d_in[0];
    const unsigned int* mask = (const unsigned int*)d_in[1];
    const float* We = (const float*)d_in[2];
    const float* be = (const float*)d_in[3];
    const float* g1 = (const float*)d_in[4];
    const float* b1 = (const float*)d_in[5];
    const float* Wq = (const float*)d_in[6];
    const float* Wk = (const float*)d_in[7];
    const float* Wv = (const float*)d_in[8];
    const float* Wo = (const float*)d_in[9];
    const float* bo = (const float*)d_in[10];
    const float* g2 = (const float*)d_in[11];
    const float* b2 = (const float*)d_in[12];
    float* out = (float*)d_out;

    k_diag<<<NRB, 128>>>(vec, mask, We, be, g1, b1);
    k_qt<<<NRB/32, 256>>>(Wq, Wk);
    k_attn<<<NRB, 128>>>(vec, mask, We, be, g1, b1);
    k_out<<<NRB/32, 256>>>(Wv, Wo, bo, g2, b2, mask, out);
    if (out_size >= 266368)
        k_masks<<<17, 256>>>(mask, out);
    (void)in_sizes; (void)n_in;
}